// round 5
// baseline (speedup 1.0000x reference)
#include <cuda_runtime.h>
#include <math.h>

#define NELEM 16384
#define KSEL  8192
#define NB    8       // CTAs == cluster size (one CGA covers the whole grid)
#define NT    1024
#define EPT   2       // NELEM / (NB*NT)
#define NBINS 4096

// ---- persistent scratch (no allocation allowed) ----
__device__ unsigned int g_hist[NBINS];
__device__ unsigned int g_bmin[NB];
__device__ unsigned int g_bmax[NB];
__device__ unsigned int g_candV[NELEM];
__device__ int          g_candI[NELEM];
__device__ unsigned int g_ccount;

// hardware cluster barrier (~400 cyc) instead of gmem spin (~3.5us)
__device__ __forceinline__ void cbar()
{
    __threadfence();   // order prior gmem writes before peers proceed
    asm volatile("barrier.cluster.arrive.aligned;" ::: "memory");
    asm volatile("barrier.cluster.wait.aligned;"   ::: "memory");
}

__global__ __launch_bounds__(NT, 1) __cluster_dims__(NB, 1, 1)
void connect_attention_cga(const float* __restrict__ x,
                           const float* __restrict__ w7,
                           float* __restrict__ out)
{
    __shared__ unsigned int sm_a[32], sm_b[32];
    __shared__ unsigned int s_lo, s_hi;
    __shared__ unsigned int s_bstar, s_cbase;

    const int tid  = threadIdx.x;
    const int lane = tid & 31;
    const int wid  = tid >> 5;
    const int gid0 = blockIdx.x * NT + tid;     // elements gid0, gid0 + 8192

    // ================= Phase A: conv + sigmoid (EPT elems/thread) =================
    const float w0 = __ldg(w7 + 0), w1 = __ldg(w7 + 1), w2 = __ldg(w7 + 2),
                w3 = __ldg(w7 + 3), w4 = __ldg(w7 + 4), w5 = __ldg(w7 + 5),
                w6 = __ldg(w7 + 6);

    float        xv[EPT], sc[EPT];
    unsigned int v[EPT];
    int          bin[EPT];

    #pragma unroll
    for (int r = 0; r < EPT; ++r) {
        const int gid = gid0 + r * (NB * NT / 1) * 1;   // gid0, gid0+8192
        const int g   = gid0 + r * NB * NT;
        const float x_i = __ldg(x + g);
        float y = x_i * w3;
        if (g >= 3)         y = fmaf(__ldg(x + g - 3), w0, y);
        if (g >= 2)         y = fmaf(__ldg(x + g - 2), w1, y);
        if (g >= 1)         y = fmaf(__ldg(x + g - 1), w2, y);
        if (g + 1 < NELEM)  y = fmaf(__ldg(x + g + 1), w4, y);
        if (g + 2 < NELEM)  y = fmaf(__ldg(x + g + 2), w5, y);
        if (g + 3 < NELEM)  y = fmaf(__ldg(x + g + 3), w6, y);
        const float s = 1.0f / (1.0f + expf(-y));
        xv[r] = x_i;
        sc[r] = s;
        v[r]  = __float_as_uint(s);     // positive: bit order == value order
        out[NELEM + g] = s;             // attention_score output
        (void)gid;
    }

    // zero shared scratch for this run (covered by bar1; graph-replay safe)
    {
        const int z = blockIdx.x * NT + tid;   // 8192 threads zero 4096 bins
        if (z < NBINS) g_hist[z] = 0;
        if (z == 0)    g_ccount = 0;
    }

    // block min/max -> per-block slots
    {
        unsigned int mn = min(v[0], v[1]);
        unsigned int mx = max(v[0], v[1]);
        mn = __reduce_min_sync(0xffffffffu, mn);
        mx = __reduce_max_sync(0xffffffffu, mx);
        if (lane == 0) { sm_a[wid] = mn; sm_b[wid] = mx; }
        __syncthreads();
        if (wid == 0) {
            unsigned int a = sm_a[lane], b = sm_b[lane];
            a = __reduce_min_sync(0xffffffffu, a);
            b = __reduce_max_sync(0xffffffffu, b);
            if (lane == 0) { g_bmin[blockIdx.x] = a; g_bmax[blockIdx.x] = b; }
        }
    }

    cbar();   // ---- bar1: min/max + zeroed hist visible ----

    // ================= Phase B: global linear histogram =================
    if (wid == 0) {
        unsigned int a = (lane < NB) ? __ldcg(&g_bmin[lane]) : 0xFFFFFFFFu;
        unsigned int b = (lane < NB) ? __ldcg(&g_bmax[lane]) : 0u;
        a = __reduce_min_sync(0xffffffffu, a);
        b = __reduce_max_sync(0xffffffffu, b);
        if (lane == 0) { s_lo = a; s_hi = b; }
    }
    __syncthreads();
    const unsigned int lo   = s_lo;
    const unsigned int span = s_hi - lo;
    const int bitlen = 32 - __clz(span | 1u);
    const int shift  = bitlen > 12 ? bitlen - 12 : 0;

    #pragma unroll
    for (int r = 0; r < EPT; ++r) {
        bin[r] = (int)((v[r] - lo) >> shift);    // < NBINS
        atomicAdd(&g_hist[bin[r]], 1u);
    }

    cbar();   // ---- bar2: histogram complete ----

    // ================= Phase C: redundant scan -> boundary bin =================
    {
        unsigned int h[NBINS / NT];
        unsigned int local = 0;
        #pragma unroll
        for (int q = 0; q < NBINS / NT; ++q) {
            h[q] = __ldcg(&g_hist[tid * (NBINS / NT) + q]);
            local += h[q];
        }
        unsigned int inc = local;
        #pragma unroll
        for (int o = 1; o < 32; o <<= 1) {
            unsigned int t = __shfl_up_sync(0xffffffffu, inc, o);
            if (lane >= o) inc += t;
        }
        if (lane == 31) sm_a[wid] = inc;
        __syncthreads();
        if (wid == 0) {
            unsigned int wsum = sm_a[lane];
            unsigned int winc = wsum;
            #pragma unroll
            for (int o = 1; o < 32; o <<= 1) {
                unsigned int t = __shfl_up_sync(0xffffffffu, winc, o);
                if (lane >= o) winc += t;
            }
            sm_b[lane] = winc - wsum;   // exclusive warp base
        }
        __syncthreads();
        unsigned int base = sm_b[wid] + inc - local;

        if (base < KSEL && base + local >= KSEL) {     // exactly one thread
            unsigned int c = base;
            #pragma unroll
            for (int q = 0; q < NBINS / NT; ++q) {
                if (c + h[q] >= KSEL) {
                    s_bstar = (unsigned)(tid * (NBINS / NT) + q);
                    s_cbase = c;
                    break;
                }
                c += h[q];
            }
        }
    }
    __syncthreads();
    const int          bstar = (int)s_bstar;
    const unsigned int jkeep = KSEL - s_cbase;   // # kept from boundary bin

    // register boundary-bin candidates (expected handful)
    #pragma unroll
    for (int r = 0; r < EPT; ++r) {
        if (bin[r] == bstar) {
            unsigned int t = atomicAdd(&g_ccount, 1u);
            g_candV[t] = v[r];
            g_candI[t] = gid0 + r * NB * NT;
        }
    }

    cbar();   // ---- bar3: candidate list complete ----

    // ================= Phase D: stable rank among candidates + emit =================
    const unsigned int nc = __ldcg(&g_ccount);
    #pragma unroll
    for (int r = 0; r < EPT; ++r) {
        const int g = gid0 + r * NB * NT;
        bool keep;
        if (bin[r] < bstar)      keep = true;
        else if (bin[r] > bstar) keep = false;
        else {
            unsigned int rank = 0;
            for (unsigned int t = 0; t < nc; ++t) {
                unsigned int vt = __ldcg(&g_candV[t]);
                int          it = __ldcg(&g_candI[t]);
                rank += (vt < v[r]) || (vt == v[r] && it < g);
            }
            keep = (rank < jkeep);
        }
        out[g] = keep ? xv[r] * (sc[r] + 1.0f) : 0.0f;
    }
}

extern "C" void kernel_launch(void* const* d_in, const int* in_sizes, int n_in,
                              void* d_out, int out_size)
{
    const float* x = (const float*)d_in[0];
    const float* w = (const float*)d_in[1];
    if (n_in >= 2 && in_sizes[0] == 7) {   // defensive input-order check
        const float* t = x; x = w; w = t;
    }
    float* out = (float*)d_out;

    connect_attention_cga<<<NB, NT>>>(x, w, out);
}

// round 6
// speedup vs baseline: 1.1800x; 1.1800x over previous
#include <cuda_runtime.h>
#include <math.h>

#define NELEM  16384
#define KSEL   8192
#define NB     8        // CTAs == cluster size (one CGA spans the grid)
#define NT     1024
#define CPB    2048     // contiguous elements per CTA
#define NBINS  16384
#define SH     12
#define LOBITS 0x3B800000u   // float bits of 2^-8; scores below this -> bin 0

// ---- persistent scratch (zero-init at module load; self-maintained per run) ----
__device__ __align__(16) unsigned int g_hist[NBINS];
__device__ uint2        g_cand[NELEM];
__device__ unsigned int g_ccount;

// HW cluster barrier; arrive defaults to .release at cluster scope, so prior
// gmem writes are visible to cluster peers after the wait (no extra fence).
__device__ __forceinline__ void cbar()
{
    asm volatile("barrier.cluster.arrive.aligned;" ::: "memory");
    asm volatile("barrier.cluster.wait.aligned;"   ::: "memory");
}

__global__ __launch_bounds__(NT, 1) __cluster_dims__(NB, 1, 1)
void connect_attention_cga2(const float* __restrict__ x,
                            const float* __restrict__ w7,
                            float* __restrict__ out)
{
    __shared__ float        sx[CPB + 6];     // x[E0-3 .. E0+CPB+2]
    __shared__ float        swt[7];
    __shared__ unsigned int sm_w[32];        // warp sums / bases
    __shared__ unsigned int s_bstar, s_cbase;

    const int tid  = threadIdx.x;
    const int lane = tid & 31;
    const int wid  = tid >> 5;
    const int E0   = (int)blockIdx.x * CPB;
    const int l0   = 2 * tid;                // local index of first owned elem
    const int e0   = E0 + l0;                // global index (even)

    if (tid < 7) swt[tid] = __ldg(w7 + tid);
    if (e0 == 0) g_ccount = 0;               // ordered before registrations by bar1

    // ---- stage x tile (+halo) into smem ----
    {
        const float2 xv = *(const float2*)(x + e0);
        sx[3 + l0]     = xv.x;
        sx[3 + l0 + 1] = xv.y;
        if (tid < 3) {
            const int gl = E0 - 3 + tid;
            sx[tid] = (gl >= 0) ? __ldg(x + gl) : 0.0f;
            const int gr = E0 + CPB + tid;
            sx[3 + CPB + tid] = (gr < NELEM) ? __ldg(x + gr) : 0.0f;
        }
    }
    __syncthreads();

    const float w0 = swt[0], w1 = swt[1], w2 = swt[2], w3 = swt[3],
                w4 = swt[4], w5 = swt[5], w6 = swt[6];

    // ---- conv 'same' + sigmoid for elems e0, e0+1 ----
    const float a0 = sx[l0],     a1 = sx[l0 + 1], a2 = sx[l0 + 2], a3 = sx[l0 + 3],
                a4 = sx[l0 + 4], a5 = sx[l0 + 5], a6 = sx[l0 + 6], a7 = sx[l0 + 7];

    float y0 = a0 * w0;
    y0 = fmaf(a1, w1, y0); y0 = fmaf(a2, w2, y0); y0 = fmaf(a3, w3, y0);
    y0 = fmaf(a4, w4, y0); y0 = fmaf(a5, w5, y0); y0 = fmaf(a6, w6, y0);
    float y1 = a1 * w0;
    y1 = fmaf(a2, w1, y1); y1 = fmaf(a3, w2, y1); y1 = fmaf(a4, w3, y1);
    y1 = fmaf(a5, w4, y1); y1 = fmaf(a6, w5, y1); y1 = fmaf(a7, w6, y1);

    const float s0 = 1.0f / (1.0f + expf(-y0));
    const float s1 = 1.0f / (1.0f + expf(-y1));
    *(float2*)(out + NELEM + e0) = make_float2(s0, s1);   // attention_score

    const unsigned int v0 = __float_as_uint(s0);   // positive: bit order == value order
    const unsigned int v1 = __float_as_uint(s1);
    const int d0 = (int)(v0 - LOBITS);
    const int d1 = (int)(v1 - LOBITS);
    const int bin0 = d0 < 0 ? 0 : (d0 >> SH);      // < NBINS (s < 1.0)
    const int bin1 = d1 < 0 ? 0 : (d1 >> SH);

    // ---- global histogram (adjacent scores are correlated: merge if same bin) ----
    if (bin0 == bin1) {
        atomicAdd(&g_hist[bin0], 2u);
    } else {
        atomicAdd(&g_hist[bin0], 1u);
        atomicAdd(&g_hist[bin1], 1u);
    }

    cbar();   // ---- bar1: histogram complete (and g_ccount reset visible) ----

    // ---- redundant per-CTA prefix scan over 16384 bins (16/thread, LDG.128) ----
    {
        unsigned int h[16];
        {
            const uint4* hp = (const uint4*)(g_hist + tid * 16);
            uint4 q0 = __ldcg(hp + 0), q1 = __ldcg(hp + 1),
                  q2 = __ldcg(hp + 2), q3 = __ldcg(hp + 3);
            h[0]=q0.x; h[1]=q0.y; h[2]=q0.z; h[3]=q0.w;
            h[4]=q1.x; h[5]=q1.y; h[6]=q1.z; h[7]=q1.w;
            h[8]=q2.x; h[9]=q2.y; h[10]=q2.z; h[11]=q2.w;
            h[12]=q3.x; h[13]=q3.y; h[14]=q3.z; h[15]=q3.w;
        }
        unsigned int local = 0;
        #pragma unroll
        for (int q = 0; q < 16; ++q) local += h[q];

        unsigned int inc = local;
        #pragma unroll
        for (int o = 1; o < 32; o <<= 1) {
            unsigned int t = __shfl_up_sync(0xffffffffu, inc, o);
            if (lane >= o) inc += t;
        }
        if (lane == 31) sm_w[wid] = inc;
        __syncthreads();
        if (wid == 0) {
            unsigned int wsum = sm_w[lane];
            unsigned int winc = wsum;
            #pragma unroll
            for (int o = 1; o < 32; o <<= 1) {
                unsigned int t = __shfl_up_sync(0xffffffffu, winc, o);
                if (lane >= o) winc += t;
            }
            sm_w[lane] = winc - wsum;    // exclusive warp base
        }
        __syncthreads();
        const unsigned int base = sm_w[wid] + inc - local;

        if (base < KSEL && base + local >= KSEL) {   // exactly one thread
            unsigned int c = base;
            #pragma unroll
            for (int q = 0; q < 16; ++q) {
                if (c + h[q] >= KSEL) { s_bstar = (unsigned)(tid * 16 + q); s_cbase = c; break; }
                c += h[q];
            }
        }
    }
    __syncthreads();
    const int          bstar = (int)s_bstar;
    const unsigned int jkeep = KSEL - s_cbase;   // boundary-bin elements to keep

    // ---- register boundary-bin candidates (expected ~10-30) ----
    if (bin0 == bstar) {
        unsigned int t = atomicAdd(&g_ccount, 1u);
        g_cand[t] = make_uint2(v0, (unsigned)e0);
    }
    if (bin1 == bstar) {
        unsigned int t = atomicAdd(&g_ccount, 1u);
        g_cand[t] = make_uint2(v1, (unsigned)(e0 + 1));
    }

    cbar();   // ---- bar2: candidate list complete (all hist reads also done) ----

    // hist re-zero for next replay (reads finished at bar2; launch boundary
    // orders this before the next run's atomics). Off the output critical path.
    ((uint2*)(g_hist + (int)blockIdx.x * (NBINS / NB)))[tid] = make_uint2(0u, 0u);

    // ---- exact stable rank among candidates + emit new_x ----
    float o0 = 0.0f, o1 = 0.0f;
    bool k0 = (bin0 < bstar), k1 = (bin1 < bstar);
    if (bin0 == bstar || bin1 == bstar) {
        const unsigned int nc = __ldcg(&g_ccount);
        unsigned int r0 = 0, r1 = 0;
        for (unsigned int t = 0; t < nc; ++t) {
            const uint2 c = __ldcg(&g_cand[t]);
            r0 += (c.x < v0) || (c.x == v0 && c.y < (unsigned)e0);
            r1 += (c.x < v1) || (c.x == v1 && c.y < (unsigned)(e0 + 1));
        }
        if (bin0 == bstar) k0 = (r0 < jkeep);
        if (bin1 == bstar) k1 = (r1 < jkeep);
    }
    if (k0) o0 = a3 * (s0 + 1.0f);    // a3 == x[e0]
    if (k1) o1 = a4 * (s1 + 1.0f);    // a4 == x[e0+1]
    *(float2*)(out + e0) = make_float2(o0, o1);
}

extern "C" void kernel_launch(void* const* d_in, const int* in_sizes, int n_in,
                              void* d_out, int out_size)
{
    const float* x = (const float*)d_in[0];
    const float* w = (const float*)d_in[1];
    if (n_in >= 2 && in_sizes[0] == 7) {   // defensive input-order check
        const float* t = x; x = w; w = t;
    }
    float* out = (float*)d_out;

    connect_attention_cga2<<<NB, NT>>>(x, w, out);
}